// round 7
// baseline (speedup 1.0000x reference)
#include <cuda_runtime.h>
#include <cuda_fp16.h>
#include <cstdint>

#define BATCH   16
#define NNODES  10000
#define HDIM    128
#define NEDGES  320000
#define NROWS   (BATCH * NNODES)      // 160000
#define NTILES  (NROWS / 128)         // 1250

// ---------------- scratch (device globals; no allocation allowed) ----------
__device__ int    g_counts[NNODES];
__device__ int    g_offsets[NNODES + 1];
__device__ int    g_cursor[NNODES];
__device__ int    g_csr[NEDGES];
__device__ int    g_tileflag[NTILES];
__device__ int    g_pctr, g_cctr;
__device__ __half g_emb16[(size_t)NROWS * HDIM];   // 41 MB fp16 copy
__device__ __half g_nbr16[(size_t)NROWS * HDIM];   // 41 MB neighbor sums
__device__ __half g_w1_16[256 * 128];
__device__ __half g_w2_16[128 * 128];

// ---------------- helpers -----------------------------------------------------
__device__ __forceinline__ uint32_t smem_u32(const void* p) {
    uint32_t a;
    asm("{ .reg .u64 t; cvta.to.shared.u64 t, %1; cvt.u32.u64 %0, t; }"
        : "=r"(a) : "l"(p));
    return a;
}
__device__ __forceinline__ void ldsm4(uint32_t* r, uint32_t a) {
    asm volatile("ldmatrix.sync.aligned.m8n8.x4.shared.b16 {%0,%1,%2,%3}, [%4];"
                 : "=r"(r[0]), "=r"(r[1]), "=r"(r[2]), "=r"(r[3]) : "r"(a));
}
__device__ __forceinline__ void ldsm4t(uint32_t* r, uint32_t a) {
    asm volatile("ldmatrix.sync.aligned.m8n8.x4.trans.shared.b16 {%0,%1,%2,%3}, [%4];"
                 : "=r"(r[0]), "=r"(r[1]), "=r"(r[2]), "=r"(r[3]) : "r"(a));
}
__device__ __forceinline__ void mma16816(float* c, const uint32_t* a,
                                         uint32_t b0, uint32_t b1) {
    asm volatile(
        "mma.sync.aligned.m16n8k16.row.col.f32.f16.f16.f32 "
        "{%0,%1,%2,%3}, {%4,%5,%6,%7}, {%8,%9}, {%0,%1,%2,%3};"
        : "+f"(c[0]), "+f"(c[1]), "+f"(c[2]), "+f"(c[3])
        : "r"(a[0]), "r"(a[1]), "r"(a[2]), "r"(a[3]), "r"(b0), "r"(b1));
}

// ---------------- zero pass -----------------------------------------------------
__global__ void zero_k() {
    int i = blockIdx.x * blockDim.x + threadIdx.x;
    if (i < NNODES) g_counts[i] = 0;
    if (i < NTILES) g_tileflag[i] = 0;
    if (i == 0) { g_pctr = 0; g_cctr = 0; }
}

// ---------------- emb fp32 -> fp16 copy, hist fused in ------------------------
__global__ __launch_bounds__(256)
void econv_hist_k(const float* __restrict__ emb, const int* __restrict__ edge) {
    size_t gid = (size_t)blockIdx.x * 256 + threadIdx.x;
    if (blockIdx.x < NEDGES / 256)
        atomicAdd(&g_counts[edge[NEDGES + gid]], 1);
    const float4* s = (const float4*)(emb) + gid * 2;
    float4 a = s[0], b = s[1];
    __half2 h0 = __float22half2_rn(make_float2(a.x, a.y));
    __half2 h1 = __float22half2_rn(make_float2(a.z, a.w));
    __half2 h2 = __float22half2_rn(make_float2(b.x, b.y));
    __half2 h3 = __float22half2_rn(make_float2(b.z, b.w));
    uint4 o;
    o.x = *(uint32_t*)&h0; o.y = *(uint32_t*)&h1;
    o.z = *(uint32_t*)&h2; o.w = *(uint32_t*)&h3;
    *((uint4*)g_emb16 + gid) = o;
}

__global__ void scan_k() {
    __shared__ int part[1024];
    const int CH = 10;
    int t = threadIdx.x;
    int local[CH];
    int s = 0;
#pragma unroll
    for (int i = 0; i < CH; i++) {
        int idx = t * CH + i;
        int v = (idx < NNODES) ? g_counts[idx] : 0;
        local[i] = s;
        s += v;
    }
    part[t] = s;
    __syncthreads();
    for (int off = 1; off < 1024; off <<= 1) {
        int v = (t >= off) ? part[t - off] : 0;
        __syncthreads();
        part[t] += v;
        __syncthreads();
    }
    int excl = (t == 0) ? 0 : part[t - 1];
#pragma unroll
    for (int i = 0; i < CH; i++) {
        int idx = t * CH + i;
        if (idx < NNODES) {
            int o = excl + local[i];
            g_offsets[idx] = o;
            g_cursor[idx]  = o;
        }
    }
    if (t == 1023) g_offsets[NNODES] = part[1023];
}
__global__ void scatter_k(const int* __restrict__ edge) {
    int e = blockIdx.x * blockDim.x + threadIdx.x;
    if (e < NEDGES) {
        int d = edge[NEDGES + e];
        int p = atomicAdd(&g_cursor[d], 1);
        g_csr[p] = edge[e];
    }
}

// ---------------- weight fp32 -> fp16 ------------------------------------------
__global__ void wconv_k(const float* __restrict__ W, __half* o16, int total) {
    int i = blockIdx.x * blockDim.x + threadIdx.x;
    if (i < total) o16[i] = __float2half_rn(W[i]);
}

// ---------------- fused persistent kernel: CTA-level role split ----------------
// blockIdx < nprod  : producer CTA — gathers tiles (row per warp, unroll-16)
// blockIdx >= nprod : consumer CTA — GEMM1+GEMM2 per tile, waits on flag
// consumer smem (160KB):
//   [0, 64K)     W1 fp16 swizzled (once)
//   [64K, 96K)   W2 fp16 swizzled (once)
//   [96K, 160K)  ctx buf: 4 chunks x 16KB ([nbr0|nbr1|emb0|emb1]); h -> chunks 0-1
#define SM_W1   0
#define SM_W2   65536
#define SM_BUF  98304
#define SMEM_FUSED 163840

__global__ __launch_bounds__(256, 1)
void fused_k(const float* __restrict__ bias1, const float* __restrict__ bias2,
             const int* __restrict__ mask, const float* __restrict__ emb32,
             float* __restrict__ outp, int nprod) {
    extern __shared__ __align__(128) char smem[];
    __shared__ int s_tile;
    int tid  = threadIdx.x;
    int lane = tid & 31;
    int wid  = tid >> 5;

    if (blockIdx.x < nprod) {
        // ======================= PRODUCER =======================
        while (true) {
            if (tid == 0) s_tile = atomicAdd(&g_pctr, 1);
            __syncthreads();
            int tile = s_tile;
            __syncthreads();
            if (tile >= NTILES) return;
            int rowBase = tile * 128;
            // 8 warps x 16 rows, row per warp, lane covers cols 4L..4L+3
            for (int rr = 0; rr < 16; rr++) {
                int row = rowBase + wid * 16 + rr;
                int b = row / NNODES;
                int n = row - b * NNODES;
                const __half* embB =
                    g_emb16 + (size_t)b * NNODES * 128 + lane * 4;
                int beg = g_offsets[n], end = g_offsets[n + 1];
                float4 acc = make_float4(0.f, 0.f, 0.f, 0.f);
                int i = beg;
                for (; i + 16 <= end; i += 16) {
                    uint2 p[16];
#pragma unroll
                    for (int q = 0; q < 16; q++)
                        p[q] = *(const uint2*)(embB +
                                (size_t)__ldg(g_csr + i + q) * 128);
#pragma unroll
                    for (int q = 0; q < 16; q++) {
                        float2 f0 = __half22float2(*(__half2*)&p[q].x);
                        float2 f1 = __half22float2(*(__half2*)&p[q].y);
                        acc.x += f0.x; acc.y += f0.y;
                        acc.z += f1.x; acc.w += f1.y;
                    }
                }
                for (; i < end; i++) {
                    uint2 p = *(const uint2*)(embB +
                              (size_t)__ldg(g_csr + i) * 128);
                    float2 f0 = __half22float2(*(__half2*)&p.x);
                    float2 f1 = __half22float2(*(__half2*)&p.y);
                    acc.x += f0.x; acc.y += f0.y; acc.z += f1.x; acc.w += f1.y;
                }
                __half2 h0 = __floats2half2_rn(acc.x, acc.y);
                __half2 h1 = __floats2half2_rn(acc.z, acc.w);
                *(uint2*)(g_nbr16 + (size_t)row * 128 + lane * 4) =
                    make_uint2(*(uint32_t*)&h0, *(uint32_t*)&h1);
            }
            __syncthreads();
            if (tid == 0) {
                __threadfence();
                atomicExch(&g_tileflag[tile], 1);
            }
        }
    }

    // ======================= CONSUMER =======================
    uint32_t sb = smem_u32(smem);
    // W1 + W2 once, swizzled: off(k,c16)=k*256+((c^(k&7))<<4)
#pragma unroll
    for (int i = 0; i < 16; i++) {
        int idx = i * 256 + tid;
        int k = idx >> 4, c = idx & 15;
        uint32_t off = (uint32_t)(k * 256 + ((c ^ (k & 7)) << 4));
        *(uint4*)(smem + SM_W1 + off) =
            *(const uint4*)(g_w1_16 + (size_t)k * 128 + c * 8);
    }
#pragma unroll
    for (int i = 0; i < 8; i++) {
        int idx = i * 256 + tid;
        int k = idx >> 4, c = idx & 15;
        uint32_t off = (uint32_t)(k * 256 + ((c ^ (k & 7)) << 4));
        *(uint4*)(smem + SM_W2 + off) =
            *(const uint4*)(g_w2_16 + (size_t)k * 128 + c * 8);
    }
    __syncthreads();

    int wm = wid & 3, wn = wid >> 2;
    int g = lane >> 2, tig = lane & 3;
    float acc[2][8][4];
    uint32_t bufu = sb + SM_BUF;
    char* buf = smem + SM_BUF;

    // stage one 64-col chunk from gmem into chunk slot (16B moves, swizzled)
    auto stage = [&](const __half* src, int rowBase, int kb, int slot) {
        char* dst = buf + slot * 16384;
#pragma unroll
        for (int it2 = 0; it2 < 4; it2++) {
            int idx = it2 * 256 + tid;
            int r = idx >> 3, c = idx & 7;
            uint32_t off = (uint32_t)(r * 128 + ((c ^ (r & 7)) << 4));
            *(uint4*)(dst + off) =
                *(const uint4*)(src + (size_t)(rowBase + r) * 128 + kb + c * 8);
        }
    };
    auto mma_block = [&](uint32_t aB, uint32_t bB, int kk, int kAbs) {
        uint32_t aF[2][4], bF[4][4];
#pragma unroll
        for (int mi = 0; mi < 2; mi++) {
            int r = wm * 32 + mi * 16 + (lane & 15);
            int c = kk * 2 + (lane >> 4);
            uint32_t off = (uint32_t)(r * 128 + ((c ^ (r & 7)) << 4));
            ldsm4(aF[mi], aB + off);
        }
#pragma unroll
        for (int q = 0; q < 4; q++) {
            int k = kAbs + (lane & 15);
            int c = (wn * 64 + q * 16 + ((lane >> 4) << 3)) >> 3;
            uint32_t boff = (uint32_t)(k * 256 + ((c ^ (k & 7)) << 4));
            ldsm4t(bF[q], bB + boff);
        }
#pragma unroll
        for (int mi = 0; mi < 2; mi++)
#pragma unroll
            for (int n8 = 0; n8 < 8; n8++)
                mma16816(acc[mi][n8], aF[mi],
                         bF[n8 >> 1][(n8 & 1) * 2],
                         bF[n8 >> 1][(n8 & 1) * 2 + 1]);
    };

    while (true) {
        if (tid == 0) s_tile = atomicAdd(&g_cctr, 1);
        __syncthreads();
        int tile = s_tile;
        __syncthreads();
        if (tile >= NTILES) return;
        int rowBase = tile * 128;

        // emb chunks (flag-independent) first
        stage(g_emb16, rowBase, 0, 2);
        stage(g_emb16, rowBase, 64, 3);

        // wait for producer
        if (tid == 0) {
            int v;
            do {
                asm volatile("ld.acquire.gpu.global.b32 %0, [%1];"
                             : "=r"(v) : "l"(&g_tileflag[tile]) : "memory");
                if (!v) __nanosleep(64);
            } while (!v);
        }
        __syncthreads();

        stage(g_nbr16, rowBase, 0, 0);
        stage(g_nbr16, rowBase, 64, 1);
        __syncthreads();

        // ---- GEMM1: K=256 over 4 resident chunks ----
#pragma unroll
        for (int mi = 0; mi < 2; mi++)
#pragma unroll
            for (int n8 = 0; n8 < 8; n8++)
#pragma unroll
                for (int q = 0; q < 4; q++) acc[mi][n8][q] = 0.f;
#pragma unroll
        for (int ch = 0; ch < 4; ch++)
#pragma unroll
            for (int kk = 0; kk < 4; kk++)
                mma_block(bufu + ch * 16384, sb + SM_W1, kk, ch * 64 + kk * 16);
        __syncthreads();

        // ---- epilogue1: relu+bias -> h fp16 into chunks 0-1 ----
#pragma unroll
        for (int mi = 0; mi < 2; mi++) {
#pragma unroll
            for (int half = 0; half < 2; half++) {
                int rl = wm * 32 + mi * 16 + g + half * 8;
#pragma unroll
                for (int n8 = 0; n8 < 8; n8++) {
                    int cidx = wn * 64 + n8 * 8 + tig * 2;
                    float x0 = fmaxf(acc[mi][n8][half * 2 + 0] + __ldg(bias1 + cidx), 0.f);
                    float x1 = fmaxf(acc[mi][n8][half * 2 + 1] + __ldg(bias1 + cidx + 1), 0.f);
                    __half2 hv = __floats2half2_rn(x0, x1);
                    uint32_t off = (uint32_t)(rl * 128 + ((n8 ^ (rl & 7)) << 4) + tig * 4);
                    *(uint32_t*)(buf + wn * 16384 + off) = *(uint32_t*)&hv;
                }
            }
        }
        __syncthreads();

        // ---- GEMM2: K=128, A = h chunks 0-1 ----
#pragma unroll
        for (int mi = 0; mi < 2; mi++)
#pragma unroll
            for (int n8 = 0; n8 < 8; n8++)
#pragma unroll
                for (int q = 0; q < 4; q++) acc[mi][n8][q] = 0.f;
#pragma unroll
        for (int ch = 0; ch < 2; ch++)
#pragma unroll
            for (int kk = 0; kk < 4; kk++)
                mma_block(bufu + ch * 16384, sb + SM_W2, kk, ch * 64 + kk * 16);

        // ---- epilogue2: bias + mask select -> out ----
#pragma unroll
        for (int mi = 0; mi < 2; mi++) {
#pragma unroll
            for (int half = 0; half < 2; half++) {
                int r = rowBase + wm * 32 + mi * 16 + g + half * 8;
                bool doImp = (mask[r] != 0);
#pragma unroll
                for (int n8 = 0; n8 < 8; n8++) {
                    int cidx = wn * 64 + n8 * 8 + tig * 2;
                    float2 v;
                    v.x = acc[mi][n8][half * 2 + 0] + __ldg(bias2 + cidx);
                    v.y = acc[mi][n8][half * 2 + 1] + __ldg(bias2 + cidx + 1);
                    if (!doImp)
                        v = *(const float2*)(emb32 + (size_t)r * 128 + cidx);
                    *(float2*)(outp + (size_t)r * 128 + cidx) = v;
                }
            }
        }
        __syncthreads();   // buf reused next tile
    }
}

// ---------------- launch -------------------------------------------------------
extern "C" void kernel_launch(void* const* d_in, const int* in_sizes, int n_in,
                              void* d_out, int out_size) {
    const float* emb  = (const float*)d_in[0];
    const int*   mask = (const int*)d_in[1];
    const int*   edge = (const int*)d_in[2];
    const float* W1   = (const float*)d_in[3];
    const float* b1   = (const float*)d_in[4];
    const float* W2   = (const float*)d_in[5];
    const float* b2   = (const float*)d_in[6];
    float*       out  = (float*)d_out;

    cudaFuncSetAttribute(fused_k,
                         cudaFuncAttributeMaxDynamicSharedMemorySize, SMEM_FUSED);
    int dev = 0, sms = 148;
    cudaGetDevice(&dev);
    cudaDeviceGetAttribute(&sms, cudaDevAttrMultiProcessorCount, dev);
    int nprod = (sms * 64 + 74) / 148;      // ~43% producers

    zero_k<<<(NNODES + 255) / 256, 256>>>();
    econv_hist_k<<<NROWS * HDIM / (256 * 8), 256>>>(emb, edge);
    scan_k<<<1, 1024>>>();
    scatter_k<<<(NEDGES + 255) / 256, 256>>>(edge);

    __half *w1p, *w2p;
    cudaGetSymbolAddress((void**)&w1p, g_w1_16);
    cudaGetSymbolAddress((void**)&w2p, g_w2_16);
    wconv_k<<<128, 256>>>(W1, w1p, 256 * 128);
    wconv_k<<<64, 256>>>(W2, w2p, 128 * 128);

    fused_k<<<sms, 256, SMEM_FUSED>>>(b1, b2, mask, emb, out, nprod);
}

// round 8
// speedup vs baseline: 1.2116x; 1.2116x over previous
#include <cuda_runtime.h>
#include <cuda_fp16.h>
#include <cstdint>

#define BATCH   16
#define NNODES  10000
#define HDIM    128
#define NEDGES  320000
#define NROWS   (BATCH * NNODES)      // 160000
#define NTILES  (NROWS / 128)         // 1250

// ---------------- scratch (device globals; no allocation allowed) ----------
__device__ int    g_counts[NNODES];
__device__ int    g_offsets[NNODES + 1];
__device__ int    g_cursor[NNODES];
__device__ int    g_csr[NEDGES];
__device__ int    g_tileflag[NTILES];   // counts gather blocks done (16 = ready)
__device__ int    g_cctr;
__device__ __half g_emb16[(size_t)NROWS * HDIM];   // 41 MB fp16 copy
__device__ __half g_nbr16[(size_t)NROWS * HDIM];   // 41 MB neighbor sums
__device__ __half g_w1_16[256 * 128];
__device__ __half g_w2_16[128 * 128];

// ---------------- helpers -----------------------------------------------------
__device__ __forceinline__ uint32_t smem_u32(const void* p) {
    uint32_t a;
    asm("{ .reg .u64 t; cvta.to.shared.u64 t, %1; cvt.u32.u64 %0, t; }"
        : "=r"(a) : "l"(p));
    return a;
}
__device__ __forceinline__ void ldsm4(uint32_t* r, uint32_t a) {
    asm volatile("ldmatrix.sync.aligned.m8n8.x4.shared.b16 {%0,%1,%2,%3}, [%4];"
                 : "=r"(r[0]), "=r"(r[1]), "=r"(r[2]), "=r"(r[3]) : "r"(a));
}
__device__ __forceinline__ void ldsm4t(uint32_t* r, uint32_t a) {
    asm volatile("ldmatrix.sync.aligned.m8n8.x4.trans.shared.b16 {%0,%1,%2,%3}, [%4];"
                 : "=r"(r[0]), "=r"(r[1]), "=r"(r[2]), "=r"(r[3]) : "r"(a));
}
__device__ __forceinline__ void mma16816(float* c, const uint32_t* a,
                                         uint32_t b0, uint32_t b1) {
    asm volatile(
        "mma.sync.aligned.m16n8k16.row.col.f32.f16.f16.f32 "
        "{%0,%1,%2,%3}, {%4,%5,%6,%7}, {%8,%9}, {%0,%1,%2,%3};"
        : "+f"(c[0]), "+f"(c[1]), "+f"(c[2]), "+f"(c[3])
        : "r"(a[0]), "r"(a[1]), "r"(a[2]), "r"(a[3]), "r"(b0), "r"(b1));
}
// one warp gathers one row into g_nbr16 (fp32 accumulate over CSR neighbors)
template <int UNROLL>
__device__ __forceinline__ void gather_row(int row, int lane) {
    int b = row / NNODES;
    int n = row - b * NNODES;
    const __half* embB = g_emb16 + (size_t)b * NNODES * 128 + lane * 4;
    int beg = g_offsets[n], end = g_offsets[n + 1];
    float4 acc = make_float4(0.f, 0.f, 0.f, 0.f);
    int i = beg;
    for (; i + UNROLL <= end; i += UNROLL) {
        uint2 p[UNROLL];
#pragma unroll
        for (int q = 0; q < UNROLL; q++)
            p[q] = *(const uint2*)(embB + (size_t)__ldg(g_csr + i + q) * 128);
#pragma unroll
        for (int q = 0; q < UNROLL; q++) {
            float2 f0 = __half22float2(*(__half2*)&p[q].x);
            float2 f1 = __half22float2(*(__half2*)&p[q].y);
            acc.x += f0.x; acc.y += f0.y; acc.z += f1.x; acc.w += f1.y;
        }
    }
    for (; i < end; i++) {
        uint2 p = *(const uint2*)(embB + (size_t)__ldg(g_csr + i) * 128);
        float2 f0 = __half22float2(*(__half2*)&p.x);
        float2 f1 = __half22float2(*(__half2*)&p.y);
        acc.x += f0.x; acc.y += f0.y; acc.z += f1.x; acc.w += f1.y;
    }
    __half2 h0 = __floats2half2_rn(acc.x, acc.y);
    __half2 h1 = __floats2half2_rn(acc.z, acc.w);
    *(uint2*)(g_nbr16 + (size_t)row * 128 + lane * 4) =
        make_uint2(*(uint32_t*)&h0, *(uint32_t*)&h1);
}

// ---------------- zero pass -----------------------------------------------------
__global__ void zero_k() {
    int i = blockIdx.x * blockDim.x + threadIdx.x;
    if (i < NNODES) g_counts[i] = 0;
    if (i < NTILES) g_tileflag[i] = 0;
    if (i == 0) g_cctr = 0;
}

// ---------------- emb fp32 -> fp16 copy, hist fused in ------------------------
__global__ __launch_bounds__(256)
void econv_hist_k(const float* __restrict__ emb, const int* __restrict__ edge) {
    size_t gid = (size_t)blockIdx.x * 256 + threadIdx.x;
    if (blockIdx.x < NEDGES / 256)
        atomicAdd(&g_counts[edge[NEDGES + gid]], 1);
    const float4* s = (const float4*)(emb) + gid * 2;
    float4 a = s[0], b = s[1];
    __half2 h0 = __float22half2_rn(make_float2(a.x, a.y));
    __half2 h1 = __float22half2_rn(make_float2(a.z, a.w));
    __half2 h2 = __float22half2_rn(make_float2(b.x, b.y));
    __half2 h3 = __float22half2_rn(make_float2(b.z, b.w));
    uint4 o;
    o.x = *(uint32_t*)&h0; o.y = *(uint32_t*)&h1;
    o.z = *(uint32_t*)&h2; o.w = *(uint32_t*)&h3;
    *((uint4*)g_emb16 + gid) = o;
}

__global__ void scan_k() {
    __shared__ int part[1024];
    const int CH = 10;
    int t = threadIdx.x;
    int local[CH];
    int s = 0;
#pragma unroll
    for (int i = 0; i < CH; i++) {
        int idx = t * CH + i;
        int v = (idx < NNODES) ? g_counts[idx] : 0;
        local[i] = s;
        s += v;
    }
    part[t] = s;
    __syncthreads();
    for (int off = 1; off < 1024; off <<= 1) {
        int v = (t >= off) ? part[t - off] : 0;
        __syncthreads();
        part[t] += v;
        __syncthreads();
    }
    int excl = (t == 0) ? 0 : part[t - 1];
#pragma unroll
    for (int i = 0; i < CH; i++) {
        int idx = t * CH + i;
        if (idx < NNODES) {
            int o = excl + local[i];
            g_offsets[idx] = o;
            g_cursor[idx]  = o;
        }
    }
    if (t == 1023) g_offsets[NNODES] = part[1023];
}
__global__ void scatter_k(const int* __restrict__ edge) {
    int e = blockIdx.x * blockDim.x + threadIdx.x;
    if (e < NEDGES) {
        int d = edge[NEDGES + e];
        int p = atomicAdd(&g_cursor[d], 1);
        g_csr[p] = edge[e];
    }
}

// ---------------- weight fp32 -> fp16 ------------------------------------------
__global__ void wconv_k(const float* __restrict__ W, __half* o16, int total) {
    int i = blockIdx.x * blockDim.x + threadIdx.x;
    if (i < total) o16[i] = __float2half_rn(W[i]);
}

// ---------------- gather kernel (R5 shape: 20000 CTAs, high occupancy) ---------
// block = 8 warps, one row per warp; after 8 rows: bump tile counter (16/tile)
__global__ __launch_bounds__(256, 4)
void gather_k() {
    int wid  = threadIdx.x >> 5;
    int lane = threadIdx.x & 31;
    int row  = blockIdx.x * 8 + wid;
    gather_row<16>(row, lane);
    __syncthreads();
    if (threadIdx.x == 0) {
        __threadfence();
        atomicAdd(&g_tileflag[blockIdx.x >> 4], 1);
    }
}

// ---------------- persistent consumer: GEMM1+GEMM2 per tile --------------------
// smem (160KB): [0,64K) W1 | [64K,96K) W2 | [96K,160K) ctx 4x16KB; h->chunks 0-1
#define SM_W1   0
#define SM_W2   65536
#define SM_BUF  98304
#define SMEM_FUSED 163840

__global__ __launch_bounds__(256, 1)
void consumer_k(const float* __restrict__ bias1, const float* __restrict__ bias2,
                const int* __restrict__ mask, const float* __restrict__ emb32,
                float* __restrict__ outp) {
    // allow the gather kernel (secondary) to launch immediately
    asm volatile("griddepcontrol.launch_dependents;");

    extern __shared__ __align__(128) char smem[];
    __shared__ int s_tile, s_need;
    int tid  = threadIdx.x;
    int lane = tid & 31;
    int wid  = tid >> 5;
    uint32_t sb = smem_u32(smem);

    // W1 + W2 once, swizzled: off(k,c16)=k*256+((c^(k&7))<<4)
#pragma unroll
    for (int i = 0; i < 16; i++) {
        int idx = i * 256 + tid;
        int k = idx >> 4, c = idx & 15;
        uint32_t off = (uint32_t)(k * 256 + ((c ^ (k & 7)) << 4));
        *(uint4*)(smem + SM_W1 + off) =
            *(const uint4*)(g_w1_16 + (size_t)k * 128 + c * 8);
    }
#pragma unroll
    for (int i = 0; i < 8; i++) {
        int idx = i * 256 + tid;
        int k = idx >> 4, c = idx & 15;
        uint32_t off = (uint32_t)(k * 256 + ((c ^ (k & 7)) << 4));
        *(uint4*)(smem + SM_W2 + off) =
            *(const uint4*)(g_w2_16 + (size_t)k * 128 + c * 8);
    }
    __syncthreads();

    int wm = wid & 3, wn = wid >> 2;
    int g = lane >> 2, tig = lane & 3;
    float acc[2][8][4];
    uint32_t bufu = sb + SM_BUF;
    char* buf = smem + SM_BUF;

    auto stage = [&](const __half* src, int rowBase, int kb, int slot) {
        char* dst = buf + slot * 16384;
#pragma unroll
        for (int it2 = 0; it2 < 4; it2++) {
            int idx = it2 * 256 + tid;
            int r = idx >> 3, c = idx & 7;
            uint32_t off = (uint32_t)(r * 128 + ((c ^ (r & 7)) << 4));
            *(uint4*)(dst + off) =
                *(const uint4*)(src + (size_t)(rowBase + r) * 128 + kb + c * 8);
        }
    };
    auto mma_block = [&](uint32_t aB, uint32_t bB, int kk, int kAbs) {
        uint32_t aF[2][4], bF[4][4];
#pragma unroll
        for (int mi = 0; mi < 2; mi++) {
            int r = wm * 32 + mi * 16 + (lane & 15);
            int c = kk * 2 + (lane >> 4);
            uint32_t off = (uint32_t)(r * 128 + ((c ^ (r & 7)) << 4));
            ldsm4(aF[mi], aB + off);
        }
#pragma unroll
        for (int q = 0; q < 4; q++) {
            int k = kAbs + (lane & 15);
            int c = (wn * 64 + q * 16 + ((lane >> 4) << 3)) >> 3;
            uint32_t boff = (uint32_t)(k * 256 + ((c ^ (k & 7)) << 4));
            ldsm4t(bF[q], bB + boff);
        }
#pragma unroll
        for (int mi = 0; mi < 2; mi++)
#pragma unroll
            for (int n8 = 0; n8 < 8; n8++)
                mma16816(acc[mi][n8], aF[mi],
                         bF[n8 >> 1][(n8 & 1) * 2],
                         bF[n8 >> 1][(n8 & 1) * 2 + 1]);
    };

    while (true) {
        if (tid == 0) s_tile = atomicAdd(&g_cctr, 1);
        __syncthreads();
        int tile = s_tile;
        __syncthreads();
        if (tile >= NTILES) return;
        int rowBase = tile * 128;

        // emb chunks first (flag-independent)
        stage(g_emb16, rowBase, 0, 2);
        stage(g_emb16, rowBase, 64, 3);

        // wait for gather of this tile (16 blocks); bounded spin + self-gather
        if (tid == 0) {
            int v = 0;
            for (int spin = 0; spin < 700; ++spin) {
                asm volatile("ld.acquire.gpu.global.b32 %0, [%1];"
                             : "=r"(v) : "l"(&g_tileflag[tile]) : "memory");
                if (v >= 16) break;
                __nanosleep(64);
            }
            s_need = (v < 16);
        }
        __syncthreads();
        if (s_need) {
            // fallback: gather this tile ourselves (idempotent with producer)
            for (int rr = 0; rr < 16; rr++)
                gather_row<8>(rowBase + wid * 16 + rr, lane);
            __syncthreads();
        }

        stage(g_nbr16, rowBase, 0, 0);
        stage(g_nbr16, rowBase, 64, 1);
        __syncthreads();

        // ---- GEMM1: K=256 over 4 resident chunks ----
#pragma unroll
        for (int mi = 0; mi < 2; mi++)
#pragma unroll
            for (int n8 = 0; n8 < 8; n8++)
#pragma unroll
                for (int q = 0; q < 4; q++) acc[mi][n8][q] = 0.f;
#pragma unroll
        for (int ch = 0; ch < 4; ch++)
#pragma unroll
            for (int kk = 0; kk < 4; kk++)
                mma_block(bufu + ch * 16384, sb + SM_W1, kk, ch * 64 + kk * 16);
        __syncthreads();

        // ---- epilogue1: relu+bias -> h fp16 into chunks 0-1 ----
#pragma unroll
        for (int mi = 0; mi < 2; mi++) {
#pragma unroll
            for (int half = 0; half < 2; half++) {
                int rl = wm * 32 + mi * 16 + g + half * 8;
#pragma unroll
                for (int n8 = 0; n8 < 8; n8++) {
                    int cidx = wn * 64 + n8 * 8 + tig * 2;
                    float x0 = fmaxf(acc[mi][n8][half * 2 + 0] + __ldg(bias1 + cidx), 0.f);
                    float x1 = fmaxf(acc[mi][n8][half * 2 + 1] + __ldg(bias1 + cidx + 1), 0.f);
                    __half2 hv = __floats2half2_rn(x0, x1);
                    uint32_t off = (uint32_t)(rl * 128 + ((n8 ^ (rl & 7)) << 4) + tig * 4);
                    *(uint32_t*)(buf + wn * 16384 + off) = *(uint32_t*)&hv;
                }
            }
        }
        __syncthreads();

        // ---- GEMM2: K=128, A = h chunks 0-1 ----
#pragma unroll
        for (int mi = 0; mi < 2; mi++)
#pragma unroll
            for (int n8 = 0; n8 < 8; n8++)
#pragma unroll
                for (int q = 0; q < 4; q++) acc[mi][n8][q] = 0.f;
#pragma unroll
        for (int ch = 0; ch < 2; ch++)
#pragma unroll
            for (int kk = 0; kk < 4; kk++)
                mma_block(bufu + ch * 16384, sb + SM_W2, kk, ch * 64 + kk * 16);

        // ---- epilogue2: bias + mask select -> out ----
#pragma unroll
        for (int mi = 0; mi < 2; mi++) {
#pragma unroll
            for (int half = 0; half < 2; half++) {
                int r = rowBase + wm * 32 + mi * 16 + g + half * 8;
                bool doImp = (mask[r] != 0);
#pragma unroll
                for (int n8 = 0; n8 < 8; n8++) {
                    int cidx = wn * 64 + n8 * 8 + tig * 2;
                    float2 v;
                    v.x = acc[mi][n8][half * 2 + 0] + __ldg(bias2 + cidx);
                    v.y = acc[mi][n8][half * 2 + 1] + __ldg(bias2 + cidx + 1);
                    if (!doImp)
                        v = *(const float2*)(emb32 + (size_t)r * 128 + cidx);
                    *(float2*)(outp + (size_t)r * 128 + cidx) = v;
                }
            }
        }
        __syncthreads();   // buf reused next tile
    }
}

// ---------------- launch -------------------------------------------------------
extern "C" void kernel_launch(void* const* d_in, const int* in_sizes, int n_in,
                              void* d_out, int out_size) {
    const float* emb  = (const float*)d_in[0];
    const int*   mask = (const int*)d_in[1];
    const int*   edge = (const int*)d_in[2];
    const float* W1   = (const float*)d_in[3];
    const float* b1   = (const float*)d_in[4];
    const float* W2   = (const float*)d_in[5];
    const float* b2   = (const float*)d_in[6];
    float*       out  = (float*)d_out;

    cudaFuncSetAttribute(consumer_k,
                         cudaFuncAttributeMaxDynamicSharedMemorySize, SMEM_FUSED);
    int dev = 0, sms = 148;
    cudaGetDevice(&dev);
    cudaDeviceGetAttribute(&sms, cudaDevAttrMultiProcessorCount, dev);
    if (sms > NTILES) sms = NTILES;

    zero_k<<<(NNODES + 255) / 256, 256>>>();
    econv_hist_k<<<NROWS * HDIM / (256 * 8), 256>>>(emb, edge);
    scan_k<<<1, 1024>>>();
    scatter_k<<<(NEDGES + 255) / 256, 256>>>(edge);

    __half *w1p, *w2p;
    cudaGetSymbolAddress((void**)&w1p, g_w1_16);
    cudaGetSymbolAddress((void**)&w2p, g_w2_16);
    wconv_k<<<128, 256>>>(W1, w1p, 256 * 128);
    wconv_k<<<64, 256>>>(W2, w2p, 128 * 128);

    // primary: persistent consumer (triggers PDL at entry)
    consumer_k<<<sms, 256, SMEM_FUSED>>>(b1, b2, mask, emb, out);

    // secondary: high-occupancy gather, overlapped via programmatic launch
    {
        cudaLaunchConfig_t cfg = {};
        cfg.gridDim  = dim3(NROWS / 8);
        cfg.blockDim = dim3(256);
        cfg.dynamicSmemBytes = 0;
        cfg.stream = 0;
        cudaLaunchAttribute at[1];
        at[0].id = cudaLaunchAttributeProgrammaticStreamSerialization;
        at[0].val.programmaticStreamSerializationAllowed = 1;
        cfg.attrs = at;
        cfg.numAttrs = 1;
        cudaLaunchKernelEx(&cfg, gather_k);
    }
}

// round 9
// speedup vs baseline: 2.3581x; 1.9463x over previous
#include <cuda_runtime.h>
#include <cuda_fp16.h>
#include <cstdint>

#define BATCH   16
#define NNODES  10000
#define HDIM    128
#define NEDGES  320000
#define NROWS   (BATCH * NNODES)      // 160000
#define NTILES  (NROWS / 128)         // 1250

// ---------------- scratch (device globals; no allocation allowed) ----------
__device__ int    g_counts[NNODES];
__device__ int    g_offsets[NNODES + 1];
__device__ int    g_cursor[NNODES];
__device__ int    g_csr[NEDGES];
__device__ int    g_cctr;
__device__ __half g_emb16[(size_t)NROWS * HDIM];   // 41 MB fp16 copy
__device__ __half g_w1_16[256 * 128];
__device__ __half g_w2_16[128 * 128];

// ---------------- helpers -----------------------------------------------------
__device__ __forceinline__ uint32_t smem_u32(const void* p) {
    uint32_t a;
    asm("{ .reg .u64 t; cvta.to.shared.u64 t, %1; cvt.u32.u64 %0, t; }"
        : "=r"(a) : "l"(p));
    return a;
}
__device__ __forceinline__ void ldsm4(uint32_t* r, uint32_t a) {
    asm volatile("ldmatrix.sync.aligned.m8n8.x4.shared.b16 {%0,%1,%2,%3}, [%4];"
                 : "=r"(r[0]), "=r"(r[1]), "=r"(r[2]), "=r"(r[3]) : "r"(a));
}
__device__ __forceinline__ void ldsm4t(uint32_t* r, uint32_t a) {
    asm volatile("ldmatrix.sync.aligned.m8n8.x4.trans.shared.b16 {%0,%1,%2,%3}, [%4];"
                 : "=r"(r[0]), "=r"(r[1]), "=r"(r[2]), "=r"(r[3]) : "r"(a));
}
__device__ __forceinline__ void mma16816(float* c, const uint32_t* a,
                                         uint32_t b0, uint32_t b1) {
    asm volatile(
        "mma.sync.aligned.m16n8k16.row.col.f32.f16.f16.f32 "
        "{%0,%1,%2,%3}, {%4,%5,%6,%7}, {%8,%9}, {%0,%1,%2,%3};"
        : "+f"(c[0]), "+f"(c[1]), "+f"(c[2]), "+f"(c[3])
        : "r"(a[0]), "r"(a[1]), "r"(a[2]), "r"(a[3]), "r"(b0), "r"(b1));
}

// ---------------- zero pass -----------------------------------------------------
__global__ void zero_k() {
    int i = blockIdx.x * blockDim.x + threadIdx.x;
    if (i < NNODES) g_counts[i] = 0;
    if (i == 0) g_cctr = 0;
}

// ---------------- emb fp32 -> fp16 copy, hist fused in ------------------------
__global__ __launch_bounds__(256)
void econv_hist_k(const float* __restrict__ emb, const int* __restrict__ edge) {
    size_t gid = (size_t)blockIdx.x * 256 + threadIdx.x;
    if (blockIdx.x < NEDGES / 256)
        atomicAdd(&g_counts[edge[NEDGES + gid]], 1);
    const float4* s = (const float4*)(emb) + gid * 2;
    float4 a = s[0], b = s[1];
    __half2 h0 = __float22half2_rn(make_float2(a.x, a.y));
    __half2 h1 = __float22half2_rn(make_float2(a.z, a.w));
    __half2 h2 = __float22half2_rn(make_float2(b.x, b.y));
    __half2 h3 = __float22half2_rn(make_float2(b.z, b.w));
    uint4 o;
    o.x = *(uint32_t*)&h0; o.y = *(uint32_t*)&h1;
    o.z = *(uint32_t*)&h2; o.w = *(uint32_t*)&h3;
    *((uint4*)g_emb16 + gid) = o;
}

__global__ void scan_k() {
    __shared__ int part[1024];
    const int CH = 10;
    int t = threadIdx.x;
    int local[CH];
    int s = 0;
#pragma unroll
    for (int i = 0; i < CH; i++) {
        int idx = t * CH + i;
        int v = (idx < NNODES) ? g_counts[idx] : 0;
        local[i] = s;
        s += v;
    }
    part[t] = s;
    __syncthreads();
    for (int off = 1; off < 1024; off <<= 1) {
        int v = (t >= off) ? part[t - off] : 0;
        __syncthreads();
        part[t] += v;
        __syncthreads();
    }
    int excl = (t == 0) ? 0 : part[t - 1];
#pragma unroll
    for (int i = 0; i < CH; i++) {
        int idx = t * CH + i;
        if (idx < NNODES) {
            int o = excl + local[i];
            g_offsets[idx] = o;
            g_cursor[idx]  = o;
        }
    }
    if (t == 1023) g_offsets[NNODES] = part[1023];
}
__global__ void scatter_k(const int* __restrict__ edge) {
    int e = blockIdx.x * blockDim.x + threadIdx.x;
    if (e < NEDGES) {
        int d = edge[NEDGES + e];
        int p = atomicAdd(&g_cursor[d], 1);
        g_csr[p] = edge[e];
    }
}

// ---------------- weight fp32 -> fp16 ------------------------------------------
__global__ void wconv_k(const float* __restrict__ W, __half* o16, int total) {
    int i = blockIdx.x * blockDim.x + threadIdx.x;
    if (i < total) o16[i] = __float2half_rn(W[i]);
}

// ---------------- fused gather+GEMM1+GEMM2 persistent kernel -------------------
// 512 threads (16 warps), 1 CTA/SM. Per tile:
//   phase A: all warps gather 128 rows into smem ctx chunks 0-1 (fp32 acc),
//            all threads copy emb into chunks 2-3
//   phase B: all warps GEMM1 (K=256) -> relu+bias -> h into chunks 0-1
//            all warps GEMM2 (K=128) -> bias+mask -> out
// smem (160KB): [0,64K) W1 | [64K,96K) W2 | [96K,160K) ctx 4x16KB
#define SM_W1   0
#define SM_W2   65536
#define SM_BUF  98304
#define SMEM_FUSED 163840

__global__ __launch_bounds__(512, 1)
void fused_k(const float* __restrict__ bias1, const float* __restrict__ bias2,
             const int* __restrict__ mask, const float* __restrict__ emb32,
             float* __restrict__ outp) {
    extern __shared__ __align__(128) char smem[];
    __shared__ int s_tile;
    int tid  = threadIdx.x;
    int lane = tid & 31;
    int wid  = tid >> 5;
    uint32_t sb = smem_u32(smem);

    // ---- W1 + W2 resident, swizzled: off(k,c16)=k*256+((c^(k&7))<<4) ----
#pragma unroll
    for (int i = 0; i < 8; i++) {
        int idx = i * 512 + tid;                 // 4096 chunks
        int k = idx >> 4, c = idx & 15;
        uint32_t off = (uint32_t)(k * 256 + ((c ^ (k & 7)) << 4));
        *(uint4*)(smem + SM_W1 + off) =
            *(const uint4*)(g_w1_16 + (size_t)k * 128 + c * 8);
    }
#pragma unroll
    for (int i = 0; i < 4; i++) {
        int idx = i * 512 + tid;                 // 2048 chunks
        int k = idx >> 4, c = idx & 15;
        uint32_t off = (uint32_t)(k * 256 + ((c ^ (k & 7)) << 4));
        *(uint4*)(smem + SM_W2 + off) =
            *(const uint4*)(g_w2_16 + (size_t)k * 128 + c * 8);
    }
    __syncthreads();

    int wm = wid & 3, wn = wid >> 2;             // 4 x 4 warp grid, 32x32 tiles
    int g = lane >> 2, tig = lane & 3;
    float acc[2][4][4];
    char* buf = smem + SM_BUF;
    uint32_t bufu = sb + SM_BUF;

    // gather smem-write coords (col = lane*4 .. lane*4+3)
    int gslot = lane >> 4;
    uint32_t gcc = (uint32_t)((lane >> 1) & 7);
    uint32_t ge8 = (uint32_t)((lane & 1) * 8);

    auto mma_block = [&](uint32_t aB, uint32_t bB, int kk, int kAbs) {
        uint32_t aF[2][4], bF[2][4];
#pragma unroll
        for (int mi = 0; mi < 2; mi++) {
            int r = wm * 32 + mi * 16 + (lane & 15);
            int c = kk * 2 + (lane >> 4);
            uint32_t off = (uint32_t)(r * 128 + ((c ^ (r & 7)) << 4));
            ldsm4(aF[mi], aB + off);
        }
#pragma unroll
        for (int q = 0; q < 2; q++) {
            int k = kAbs + (lane & 15);
            int c = (wn * 32 + q * 16 + ((lane >> 4) << 3)) >> 3;
            uint32_t boff = (uint32_t)(k * 256 + ((c ^ (k & 7)) << 4));
            ldsm4t(bF[q], bB + boff);
        }
#pragma unroll
        for (int mi = 0; mi < 2; mi++)
#pragma unroll
            for (int n8 = 0; n8 < 4; n8++)
                mma16816(acc[mi][n8], aF[mi],
                         bF[n8 >> 1][(n8 & 1) * 2],
                         bF[n8 >> 1][(n8 & 1) * 2 + 1]);
    };

    while (true) {
        if (tid == 0) s_tile = atomicAdd(&g_cctr, 1);
        __syncthreads();
        int tile = s_tile;
        if (tile >= NTILES) return;
        int rowBase = tile * 128;

        // ======== phase A: emb copy (chunks 2-3) + gather (chunks 0-1) ========
#pragma unroll
        for (int it = 0; it < 4; it++) {
            int idx = it * 512 + tid;            // 2048 chunks
            int r = idx >> 4, c = idx & 15;
            uint32_t off = (uint32_t)(r * 128 + (((c & 7) ^ (r & 7)) << 4));
            *(uint4*)(buf + (2 + (c >> 3)) * 16384 + off) =
                *(const uint4*)(g_emb16 + (size_t)(rowBase + r) * 128 + c * 8);
        }
#pragma unroll 1
        for (int rr = 0; rr < 8; rr++) {
            int local = wid * 8 + rr;
            int row = rowBase + local;
            int b = row / NNODES;
            int n = row - b * NNODES;
            const __half* embB = g_emb16 + (size_t)b * NNODES * 128 + lane * 4;
            int beg = g_offsets[n], end = g_offsets[n + 1];
            float4 acg = make_float4(0.f, 0.f, 0.f, 0.f);
            int i = beg;
            for (; i + 16 <= end; i += 16) {
                uint2 p[16];
#pragma unroll
                for (int q = 0; q < 16; q++)
                    p[q] = *(const uint2*)(embB +
                            (size_t)__ldg(g_csr + i + q) * 128);
#pragma unroll
                for (int q = 0; q < 16; q++) {
                    float2 f0 = __half22float2(*(__half2*)&p[q].x);
                    float2 f1 = __half22float2(*(__half2*)&p[q].y);
                    acg.x += f0.x; acg.y += f0.y; acg.z += f1.x; acg.w += f1.y;
                }
            }
            for (; i < end; i++) {
                uint2 p = *(const uint2*)(embB + (size_t)__ldg(g_csr + i) * 128);
                float2 f0 = __half22float2(*(__half2*)&p.x);
                float2 f1 = __half22float2(*(__half2*)&p.y);
                acg.x += f0.x; acg.y += f0.y; acg.z += f1.x; acg.w += f1.y;
            }
            __half2 h0 = __floats2half2_rn(acg.x, acg.y);
            __half2 h1 = __floats2half2_rn(acg.z, acg.w);
            uint32_t off = (uint32_t)(local * 128 + ((gcc ^ (local & 7)) << 4) + ge8);
            *(uint2*)(buf + gslot * 16384 + off) =
                make_uint2(*(uint32_t*)&h0, *(uint32_t*)&h1);
        }
        __syncthreads();

        // ======== phase B: GEMM1 (K=256) ========
#pragma unroll
        for (int mi = 0; mi < 2; mi++)
#pragma unroll
            for (int n8 = 0; n8 < 4; n8++)
#pragma unroll
                for (int q = 0; q < 4; q++) acc[mi][n8][q] = 0.f;
#pragma unroll
        for (int ch = 0; ch < 4; ch++)
#pragma unroll
            for (int kk = 0; kk < 4; kk++)
                mma_block(bufu + ch * 16384, sb + SM_W1, kk, ch * 64 + kk * 16);
        __syncthreads();

        // epilogue1: relu+bias -> h fp16 into chunks 0-1
#pragma unroll
        for (int mi = 0; mi < 2; mi++) {
#pragma unroll
            for (int half = 0; half < 2; half++) {
                int rl = wm * 32 + mi * 16 + g + half * 8;
#pragma unroll
                for (int n8 = 0; n8 < 4; n8++) {
                    int cidx = wn * 32 + n8 * 8 + tig * 2;
                    float x0 = fmaxf(acc[mi][n8][half * 2 + 0] + __ldg(bias1 + cidx), 0.f);
                    float x1 = fmaxf(acc[mi][n8][half * 2 + 1] + __ldg(bias1 + cidx + 1), 0.f);
                    __half2 hv = __floats2half2_rn(x0, x1);
                    int slot = cidx >> 6;
                    uint32_t cc = (uint32_t)((cidx >> 3) & 7);
                    uint32_t off = (uint32_t)(rl * 128 + ((cc ^ (rl & 7)) << 4) +
                                              (cidx & 7) * 2);
                    *(uint32_t*)(buf + slot * 16384 + off) = *(uint32_t*)&hv;
                }
            }
        }
        __syncthreads();

        // GEMM2: K=128, A = h chunks 0-1
#pragma unroll
        for (int mi = 0; mi < 2; mi++)
#pragma unroll
            for (int n8 = 0; n8 < 4; n8++)
#pragma unroll
                for (int q = 0; q < 4; q++) acc[mi][n8][q] = 0.f;
#pragma unroll
        for (int ch = 0; ch < 2; ch++)
#pragma unroll
            for (int kk = 0; kk < 4; kk++)
                mma_block(bufu + ch * 16384, sb + SM_W2, kk, ch * 64 + kk * 16);

        // epilogue2: bias + mask select -> out
#pragma unroll
        for (int mi = 0; mi < 2; mi++) {
#pragma unroll
            for (int half = 0; half < 2; half++) {
                int r = rowBase + wm * 32 + mi * 16 + g + half * 8;
                bool doImp = (mask[r] != 0);
#pragma unroll
                for (int n8 = 0; n8 < 4; n8++) {
                    int cidx = wn * 32 + n8 * 8 + tig * 2;
                    float2 v;
                    v.x = acc[mi][n8][half * 2 + 0] + __ldg(bias2 + cidx);
                    v.y = acc[mi][n8][half * 2 + 1] + __ldg(bias2 + cidx + 1);
                    if (!doImp)
                        v = *(const float2*)(emb32 + (size_t)r * 128 + cidx);
                    *(float2*)(outp + (size_t)r * 128 + cidx) = v;
                }
            }
        }
        __syncthreads();   // ctx buf reused next tile
    }
}

// ---------------- launch -------------------------------------------------------
extern "C" void kernel_launch(void* const* d_in, const int* in_sizes, int n_in,
                              void* d_out, int out_size) {
    const float* emb  = (const float*)d_in[0];
    const int*   mask = (const int*)d_in[1];
    const int*   edge = (const int*)d_in[2];
    const float* W1   = (const float*)d_in[3];
    const float* b1   = (const float*)d_in[4];
    const float* W2   = (const float*)d_in[5];
    const float* b2   = (const float*)d_in[6];
    float*       out  = (float*)d_out;

    cudaFuncSetAttribute(fused_k,
                         cudaFuncAttributeMaxDynamicSharedMemorySize, SMEM_FUSED);
    int dev = 0, sms = 148;
    cudaGetDevice(&dev);
    cudaDeviceGetAttribute(&sms, cudaDevAttrMultiProcessorCount, dev);
    if (sms > NTILES) sms = NTILES;

    zero_k<<<(NNODES + 255) / 256, 256>>>();
    econv_hist_k<<<NROWS * HDIM / (256 * 8), 256>>>(emb, edge);
    scan_k<<<1, 1024>>>();
    scatter_k<<<(NEDGES + 255) / 256, 256>>>(edge);

    __half *w1p, *w2p;
    cudaGetSymbolAddress((void**)&w1p, g_w1_16);
    cudaGetSymbolAddress((void**)&w2p, g_w2_16);
    wconv_k<<<128, 256>>>(W1, w1p, 256 * 128);
    wconv_k<<<64, 256>>>(W2, w2p, 128 * 128);

    fused_k<<<sms, 512, SMEM_FUSED>>>(b1, b2, mask, emb, out);
}